// round 12
// baseline (speedup 1.0000x reference)
#include <cuda_runtime.h>

// Problem dims (fixed by the dataset)
#define B_   32
#define T_   512
#define IN_  512
#define H_   1024
#define OUT_ 512

// ---------------------------------------------------------------------------
// Device scratch (allocation-free rule: __device__ globals)
// ---------------------------------------------------------------------------
__device__ float g_xp[(size_t)B_ * T_ * H_];   // x@Wx + bx + bh, [B][T][H]
__device__ float g_hs[(size_t)B_ * T_ * H_];   // hidden states   [B][T][H]
__device__ float g_hx[2][H_ * B_];             // h exchange ping-pong, [j][b]
__device__ unsigned g_bar = 0;                 // grid barrier counter (flat)

// ---------------------------------------------------------------------------
// f32x2 packed math helpers
// ---------------------------------------------------------------------------
__device__ __forceinline__ unsigned long long ffma2(unsigned long long a,
                                                    unsigned long long b,
                                                    unsigned long long c) {
    unsigned long long d;
    asm("fma.rn.f32x2 %0, %1, %2, %3;" : "=l"(d) : "l"(a), "l"(b), "l"(c));
    return d;
}
__device__ __forceinline__ unsigned long long add2(unsigned long long a,
                                                   unsigned long long b) {
    unsigned long long d;
    asm("add.rn.f32x2 %0, %1, %2;" : "=l"(d) : "l"(a), "l"(b));
    return d;
}
__device__ __forceinline__ unsigned long long splat2(float x) {
    unsigned long long d;
    asm("mov.b64 %0, {%1, %2};" : "=l"(d) : "f"(x), "f"(x));
    return d;
}
__device__ __forceinline__ float2 unpack2(unsigned long long d) {
    float2 r;
    asm("mov.b64 {%0, %1}, %2;" : "=f"(r.x), "=f"(r.y) : "l"(d));
    return r;
}
__device__ __forceinline__ void cpasync16(unsigned s, const float* g) {
    asm volatile("cp.async.ca.shared.global [%0], [%1], 16;"
                 :: "r"(s), "l"(g) : "memory");
}

// ---------------------------------------------------------------------------
// SGEMM with bias epilogue, v3 (proven R11: 405us/launch): cp.async
// double-buffered B, register-staged A, 2 blocks/SM.
// Also resets the grid-barrier counter (runs before the scan kernel).
// ---------------------------------------------------------------------------
__global__ __launch_bounds__(256, 2) void sgemm_bias_kernel(
    const float* __restrict__ A, const float* __restrict__ Bm,
    const float* __restrict__ b1p, const float* __restrict__ b2p,
    float* __restrict__ C, int M, int N, int K)
{
    if (blockIdx.x == 0 && blockIdx.y == 0 && threadIdx.x == 0) g_bar = 0u;

    __shared__ __align__(16) float As[2][16][128];
    __shared__ __align__(16) float Bs[2][16][128];

    const int tid  = threadIdx.x;
    const int row0 = blockIdx.y * 128;
    const int col0 = blockIdx.x * 128;
    const int tx   = tid & 15;
    const int ty   = tid >> 4;

    const int aRow = tid >> 2;
    const int aK4  = (tid & 3) * 4;
    const int bRow = tid >> 5;
    const int bCol = (tid & 31) * 4;

    const unsigned bs0 = (unsigned)__cvta_generic_to_shared(&Bs[0][bRow][bCol]);
    const unsigned bs1 = (unsigned)__cvta_generic_to_shared(&Bs[0][bRow + 8][bCol]);
    const unsigned BUFB = 16 * 128 * 4;

    unsigned long long acc[8][4];
#pragma unroll
    for (int i = 0; i < 8; i++)
#pragma unroll
        for (int j = 0; j < 4; j++) acc[i][j] = 0ull;

    float4 av0, av1;
    const int nIter = K >> 4;

    cpasync16(bs0, Bm + (size_t)bRow * N + col0 + bCol);
    cpasync16(bs1, Bm + (size_t)(bRow + 8) * N + col0 + bCol);
    asm volatile("cp.async.commit_group;" ::: "memory");
    av0 = *(const float4*)(A + (size_t)(row0 + aRow)      * K + aK4);
    av1 = *(const float4*)(A + (size_t)(row0 + aRow + 64) * K + aK4);
    As[0][aK4 + 0][aRow] = av0.x;  As[0][aK4 + 1][aRow] = av0.y;
    As[0][aK4 + 2][aRow] = av0.z;  As[0][aK4 + 3][aRow] = av0.w;
    As[0][aK4 + 0][aRow + 64] = av1.x;  As[0][aK4 + 1][aRow + 64] = av1.y;
    As[0][aK4 + 2][aRow + 64] = av1.z;  As[0][aK4 + 3][aRow + 64] = av1.w;

    for (int it = 0; it < nIter; it++) {
        const int cur = it & 1;

        if (it + 1 < nIter) {
            const int k1 = (it + 1) << 4;
            const unsigned off = (unsigned)(cur ^ 1) * BUFB;
            cpasync16(bs0 + off, Bm + (size_t)(k1 + bRow)     * N + col0 + bCol);
            cpasync16(bs1 + off, Bm + (size_t)(k1 + bRow + 8) * N + col0 + bCol);
            asm volatile("cp.async.commit_group;" ::: "memory");
            av0 = *(const float4*)(A + (size_t)(row0 + aRow)      * K + k1 + aK4);
            av1 = *(const float4*)(A + (size_t)(row0 + aRow + 64) * K + k1 + aK4);
            asm volatile("cp.async.wait_group 1;" ::: "memory");
        } else {
            asm volatile("cp.async.wait_group 0;" ::: "memory");
        }
        __syncthreads();

#pragma unroll
        for (int kk = 0; kk < 16; kk++) {
            float4 a0 = *(const float4*)&As[cur][kk][ty * 8];
            float4 a1 = *(const float4*)&As[cur][kk][ty * 8 + 4];
            const ulonglong2* bp = (const ulonglong2*)&Bs[cur][kk][tx * 8];
            ulonglong2 b01 = bp[0];
            ulonglong2 b23 = bp[1];
            float av[8] = {a0.x, a0.y, a0.z, a0.w, a1.x, a1.y, a1.z, a1.w};
#pragma unroll
            for (int i = 0; i < 8; i++) {
                unsigned long long a2 = splat2(av[i]);
                acc[i][0] = ffma2(a2, b01.x, acc[i][0]);
                acc[i][1] = ffma2(a2, b01.y, acc[i][1]);
                acc[i][2] = ffma2(a2, b23.x, acc[i][2]);
                acc[i][3] = ffma2(a2, b23.y, acc[i][3]);
            }
        }

        if (it + 1 < nIter) {
            const int nb = cur ^ 1;
            As[nb][aK4 + 0][aRow] = av0.x;  As[nb][aK4 + 1][aRow] = av0.y;
            As[nb][aK4 + 2][aRow] = av0.z;  As[nb][aK4 + 3][aRow] = av0.w;
            As[nb][aK4 + 0][aRow + 64] = av1.x;  As[nb][aK4 + 1][aRow + 64] = av1.y;
            As[nb][aK4 + 2][aRow + 64] = av1.z;  As[nb][aK4 + 3][aRow + 64] = av1.w;
        }
        __syncthreads();
    }

    const int crow = row0 + ty * 8;
    const int ccol = col0 + tx * 8;
    float bsum[8];
#pragma unroll
    for (int j = 0; j < 8; j++) {
        float bv = b1p[ccol + j];
        if (b2p) bv += b2p[ccol + j];
        bsum[j] = bv;
    }
#pragma unroll
    for (int i = 0; i < 8; i++) {
        float o[8];
#pragma unroll
        for (int j4 = 0; j4 < 4; j4++) {
            float2 v = unpack2(acc[i][j4]);
            o[2 * j4]     = v.x + bsum[2 * j4];
            o[2 * j4 + 1] = v.y + bsum[2 * j4 + 1];
        }
        float4* cp = (float4*)(C + (size_t)(crow + i) * N + ccol);
        cp[0] = make_float4(o[0], o[1], o[2], o[3]);
        cp[1] = make_float4(o[4], o[5], o[6], o[7]);
    }
}

// ---------------------------------------------------------------------------
// h0 transpose: [B][H] -> g_hx[1] in [j][b] layout.  (scan step t=0 reads
// buffer (t+1)&1 = 1).  Also redundantly resets the barrier counter.
// ---------------------------------------------------------------------------
__global__ void h0_transpose_kernel(const float* __restrict__ h0)
{
    if (blockIdx.x == 0 && threadIdx.x == 0) g_bar = 0u;
    int idx = blockIdx.x * 256 + threadIdx.x;   // 32768 total
    int b = idx >> 10;
    int j = idx & 1023;
    g_hx[1][j * B_ + b] = h0[idx];
}

// ---------------------------------------------------------------------------
// Persistent RNN scan kernel, v6: 2-D (batch-group x j-group) work split.
//
// grid = 128 = 4 bg x 32 jg; block owns 8 batches x 32 j-columns.
// Per-block L2 h traffic: 32KB/step (was 128KB) -> 4MB/step chip-wide (4x cut).
// smem: Wh slab [1024][32j] = 128KB + staged h slice [1024][8b] = 32KB
// (160KB dynamic, opt-in) + red 16KB static.
// Thread map: warp = ks (16 k-splits of 64), lane = (jq=lane>>3, lb=lane&7).
// Per step: cooperative __ldcg stage of h slice (4x LDG.128/thread, L2-only,
// no L1-staleness hazard) -> smem compute -> red[ks][q][lane] reduction
// (conflict-free) -> tanh -> [j][b] store -> flat release/acquire barrier
// with history stores between arrive and poll (proven R11 pattern).
// ---------------------------------------------------------------------------
__global__ __launch_bounds__(512, 1) void rnn_scan_kernel(
    const float* __restrict__ Wh,   // [H][H]
    float* __restrict__ next_h)     // [B][H]
{
    extern __shared__ __align__(16) float sdyn[];
    float* whs = sdyn;               // [1024][32] = 128KB  (Wh slab)
    float* hsm = sdyn + H_ * 32;     // [1024][8]  = 32KB   (staged h slice)
    __shared__ __align__(16) unsigned long long red[16][4][32];   // 16KB

    const int tid  = threadIdx.x;
    const int ks   = tid >> 5;        // 0..15 k-split (warp)
    const int lane = tid & 31;
    const int jq   = lane >> 3;       // 0..3  j-quad within block
    const int lb   = lane & 7;        // 0..7  batch within group
    const int bg   = blockIdx.x >> 5; // 0..3  batch group
    const int jg   = blockIdx.x & 31; // 0..31 j group
    const int jbase = jg * 32;
    const int b0    = bg * 8;
    const int k0    = ks * 64;

    // Load this block's Wh slab [k][32 local j] once (step-invariant).
    for (int idx = tid; idx < H_ * 32; idx += 512)
        whs[idx] = Wh[(size_t)(idx >> 5) * H_ + jbase + (idx & 31)];
    __syncthreads();

    const float* wb = whs + k0 * 32 + jq * 8;   // this thread's weight column

    // reduction role (tid < 128): q = warp, lane -> (rjq, rlb)
    const int rq   = tid >> 5;
    const int rjq  = (tid & 31) >> 3;
    const int rlb  = tid & 7;
    const int rj0  = jbase + rjq * 8 + rq * 2;
    const int rb   = b0 + rlb;

    unsigned* bar_ptr = &g_bar;
    unsigned  target  = gridDim.x;

    for (int t = 0; t < T_; t++) {
        const float* hxg = g_hx[(t + 1) & 1];
        float*       hw  = g_hx[t & 1];

        // ---- cooperative stage: h[1024][b0..b0+8) -> hsm (L2-only loads) ----
#pragma unroll
        for (int r = 0; r < 4; r++) {
            int s = tid + r * 512;          // 2048 float4 slots
            int k = s >> 1, half = s & 1;
            float4 v = __ldcg((const float4*)(hxg + k * B_ + b0 + half * 4));
            *(float4*)(hsm + k * 8 + half * 4) = v;
        }

        // xp prefetch for this step (reduction threads; overlaps the stage)
        unsigned long long xpv = 0ull;
        if (tid < 128)
            xpv = *(const unsigned long long*)
                  (g_xp + (size_t)rb * (T_ * H_) + t * H_ + rj0);

        __syncthreads();   // hsm ready

        unsigned long long a0 = 0ull, a1 = 0ull, a2 = 0ull, a3 = 0ull;
#pragma unroll
        for (int k = 0; k < 64; k++) {
            float hv = hsm[(k0 + k) * 8 + lb];          // broadcast LDS
            ulonglong2 w01 = *(const ulonglong2*)(wb + k * 32);
            ulonglong2 w23 = *(const ulonglong2*)(wb + k * 32 + 4);
            unsigned long long s_ = splat2(hv);
            a0 = ffma2(s_, w01.x, a0);  a1 = ffma2(s_, w01.y, a1);
            a2 = ffma2(s_, w23.x, a2);  a3 = ffma2(s_, w23.y, a3);
        }

        // partials -> smem  red[ks][q][lane] (dense, conflict-free both ways)
        red[ks][0][lane] = a0;  red[ks][1][lane] = a1;
        red[ks][2][lane] = a2;  red[ks][3][lane] = a3;
        __syncthreads();

        float2 v = make_float2(0.f, 0.f);
        if (tid < 128) {
            unsigned long long s0 = add2(red[0][rq][tid & 31],  red[1][rq][tid & 31]);
            unsigned long long s1 = add2(red[2][rq][tid & 31],  red[3][rq][tid & 31]);
            unsigned long long s2 = add2(red[4][rq][tid & 31],  red[5][rq][tid & 31]);
            unsigned long long s3 = add2(red[6][rq][tid & 31],  red[7][rq][tid & 31]);
            unsigned long long s4 = add2(red[8][rq][tid & 31],  red[9][rq][tid & 31]);
            unsigned long long s5 = add2(red[10][rq][tid & 31], red[11][rq][tid & 31]);
            unsigned long long s6 = add2(red[12][rq][tid & 31], red[13][rq][tid & 31]);
            unsigned long long s7 = add2(red[14][rq][tid & 31], red[15][rq][tid & 31]);
            unsigned long long s  = add2(add2(add2(s0, s1), add2(s2, s3)),
                                         add2(add2(s4, s5), add2(s6, s7)));
            s = add2(s, xpv);

            v = unpack2(s);
            v.x = tanhf(v.x);
            v.y = tanhf(v.y);

            // exchange-buffer store ([j][b]) — critical path
            hw[rj0 * B_ + rb]       = v.x;
            hw[(rj0 + 1) * B_ + rb] = v.y;
        }

        // ---- grid barrier (release arrival, acquire poll) ----
        __syncthreads();
        if (tid == 0) {
            asm volatile("red.release.gpu.global.add.u32 [%0], %1;"
                         :: "l"(bar_ptr), "r"(1u) : "memory");
        }
        // history stores between arrive and poll: off the inter-SM path
        if (tid < 128) {
            *(float2*)(g_hs + (size_t)rb * (T_ * H_) + t * H_ + rj0) = v;
            if (t == T_ - 1)
                *(float2*)(next_h + rb * H_ + rj0) = v;
        }
        if (tid == 0) {
            unsigned e;
            while (1) {
                asm volatile("ld.acquire.gpu.global.u32 %0, [%1];"
                             : "=r"(e) : "l"(bar_ptr) : "memory");
                if (e >= target) break;
                __nanosleep(32);
            }
        }
        __syncthreads();
        target += gridDim.x;
    }
}

// ---------------------------------------------------------------------------
// kernel_launch: 5 launches, graph-capturable, default stream.
// Inputs: 0:x 1:h 2:Wx 3:bx 4:Wh 5:bh 6:W1 7:b1 8:W2 9:b2
// Output: [td0 (B*T*OUT) | td1 (B*T*OUT) | next_h (B*H)]
// ---------------------------------------------------------------------------
extern "C" void kernel_launch(void* const* d_in, const int* in_sizes, int n_in,
                              void* d_out, int out_size)
{
    (void)in_sizes; (void)n_in; (void)out_size;
    const float* x  = (const float*)d_in[0];
    const float* h  = (const float*)d_in[1];
    const float* Wx = (const float*)d_in[2];
    const float* bx = (const float*)d_in[3];
    const float* Wh = (const float*)d_in[4];
    const float* bh = (const float*)d_in[5];
    const float* W1 = (const float*)d_in[6];
    const float* b1 = (const float*)d_in[7];
    const float* W2 = (const float*)d_in[8];
    const float* b2 = (const float*)d_in[9];
    float* out = (float*)d_out;

    float* xp = nullptr;
    float* hs = nullptr;
    cudaGetSymbolAddress((void**)&xp, g_xp);
    cudaGetSymbolAddress((void**)&hs, g_hs);

    const int MT = B_ * T_;   // 16384
    const int SCAN_SMEM = (H_ * 32 + H_ * 8) * (int)sizeof(float);   // 160KB

    // opt-in to >48KB dynamic smem for the scan kernel (idempotent host call)
    cudaFuncSetAttribute(rnn_scan_kernel,
                         cudaFuncAttributeMaxDynamicSharedMemorySize, SCAN_SMEM);

    // Phase 0: Xp = x @ Wx + (bx + bh).   M=16384, N=1024, K=512
    {
        dim3 grid(H_ / 128, MT / 128);
        sgemm_bias_kernel<<<grid, 256>>>(x, Wx, bx, bh, xp, MT, H_, IN_);
    }

    // Phase 0b: transpose h0 into the [j][b] exchange buffer (+ barrier reset).
    h0_transpose_kernel<<<(B_ * H_) / 256, 256>>>(h);

    // Phase 1: sequential scan (persistent kernel, flat grid barrier).
    {
        float* next_h = out + (size_t)2 * MT * OUT_;
        rnn_scan_kernel<<<128, 512, SCAN_SMEM>>>(Wh, next_h);
    }

    // Phase 2: td0 = hs @ W1 + b1 ; td1 = hs @ W2 + b2.  M=16384, N=512, K=1024
    {
        dim3 grid(OUT_ / 128, MT / 128);
        sgemm_bias_kernel<<<grid, 256>>>(hs, W1, b1, nullptr, out, MT, OUT_, H_);
        sgemm_bias_kernel<<<grid, 256>>>(hs, W2, b2, nullptr,
                                         out + (size_t)MT * OUT_, MT, OUT_, H_);
    }
}

// round 13
// speedup vs baseline: 1.1114x; 1.1114x over previous
#include <cuda_runtime.h>

// Problem dims (fixed by the dataset)
#define B_   32
#define T_   512
#define IN_  512
#define H_   1024
#define OUT_ 512

// ---------------------------------------------------------------------------
// Device scratch (allocation-free rule: __device__ globals)
// ---------------------------------------------------------------------------
__device__ float g_xp[(size_t)B_ * T_ * H_];   // x@Wx + bx + bh, [B][T][H]
__device__ float g_hs[(size_t)B_ * T_ * H_];   // hidden states   [B][T][H]
__device__ float g_hx[2][H_ * B_];             // h exchange ping-pong, [j][b]
__device__ unsigned g_bar = 0;                 // grid barrier counter (flat)

// ---------------------------------------------------------------------------
// f32x2 packed math helpers
// ---------------------------------------------------------------------------
__device__ __forceinline__ unsigned long long ffma2(unsigned long long a,
                                                    unsigned long long b,
                                                    unsigned long long c) {
    unsigned long long d;
    asm("fma.rn.f32x2 %0, %1, %2, %3;" : "=l"(d) : "l"(a), "l"(b), "l"(c));
    return d;
}
__device__ __forceinline__ unsigned long long add2(unsigned long long a,
                                                   unsigned long long b) {
    unsigned long long d;
    asm("add.rn.f32x2 %0, %1, %2;" : "=l"(d) : "l"(a), "l"(b));
    return d;
}
__device__ __forceinline__ unsigned long long splat2(float x) {
    unsigned long long d;
    asm("mov.b64 %0, {%1, %2};" : "=l"(d) : "f"(x), "f"(x));
    return d;
}
__device__ __forceinline__ float2 unpack2(unsigned long long d) {
    float2 r;
    asm("mov.b64 {%0, %1}, %2;" : "=f"(r.x), "=f"(r.y) : "l"(d));
    return r;
}
__device__ __forceinline__ void cpasync16(unsigned s, const float* g) {
    asm volatile("cp.async.ca.shared.global [%0], [%1], 16;"
                 :: "r"(s), "l"(g) : "memory");
}

// ---------------------------------------------------------------------------
// No-op prelude kernel: shifts harness launch indices so ncu's "-s 5 -c 1"
// captures the SCAN kernel (launch #6) instead of a GEMM.
// ---------------------------------------------------------------------------
__global__ void noop_kernel() {}

// ---------------------------------------------------------------------------
// SGEMM with bias epilogue, v3 (proven R11: 405us/launch): cp.async
// double-buffered B, register-staged A, 2 blocks/SM.
// Also resets the grid-barrier counter (runs before the scan kernel).
// ---------------------------------------------------------------------------
__global__ __launch_bounds__(256, 2) void sgemm_bias_kernel(
    const float* __restrict__ A, const float* __restrict__ Bm,
    const float* __restrict__ b1p, const float* __restrict__ b2p,
    float* __restrict__ C, int M, int N, int K)
{
    if (blockIdx.x == 0 && blockIdx.y == 0 && threadIdx.x == 0) g_bar = 0u;

    __shared__ __align__(16) float As[2][16][128];
    __shared__ __align__(16) float Bs[2][16][128];

    const int tid  = threadIdx.x;
    const int row0 = blockIdx.y * 128;
    const int col0 = blockIdx.x * 128;
    const int tx   = tid & 15;
    const int ty   = tid >> 4;

    const int aRow = tid >> 2;
    const int aK4  = (tid & 3) * 4;
    const int bRow = tid >> 5;
    const int bCol = (tid & 31) * 4;

    const unsigned bs0 = (unsigned)__cvta_generic_to_shared(&Bs[0][bRow][bCol]);
    const unsigned bs1 = (unsigned)__cvta_generic_to_shared(&Bs[0][bRow + 8][bCol]);
    const unsigned BUFB = 16 * 128 * 4;

    unsigned long long acc[8][4];
#pragma unroll
    for (int i = 0; i < 8; i++)
#pragma unroll
        for (int j = 0; j < 4; j++) acc[i][j] = 0ull;

    float4 av0, av1;
    const int nIter = K >> 4;

    cpasync16(bs0, Bm + (size_t)bRow * N + col0 + bCol);
    cpasync16(bs1, Bm + (size_t)(bRow + 8) * N + col0 + bCol);
    asm volatile("cp.async.commit_group;" ::: "memory");
    av0 = *(const float4*)(A + (size_t)(row0 + aRow)      * K + aK4);
    av1 = *(const float4*)(A + (size_t)(row0 + aRow + 64) * K + aK4);
    As[0][aK4 + 0][aRow] = av0.x;  As[0][aK4 + 1][aRow] = av0.y;
    As[0][aK4 + 2][aRow] = av0.z;  As[0][aK4 + 3][aRow] = av0.w;
    As[0][aK4 + 0][aRow + 64] = av1.x;  As[0][aK4 + 1][aRow + 64] = av1.y;
    As[0][aK4 + 2][aRow + 64] = av1.z;  As[0][aK4 + 3][aRow + 64] = av1.w;

    for (int it = 0; it < nIter; it++) {
        const int cur = it & 1;

        if (it + 1 < nIter) {
            const int k1 = (it + 1) << 4;
            const unsigned off = (unsigned)(cur ^ 1) * BUFB;
            cpasync16(bs0 + off, Bm + (size_t)(k1 + bRow)     * N + col0 + bCol);
            cpasync16(bs1 + off, Bm + (size_t)(k1 + bRow + 8) * N + col0 + bCol);
            asm volatile("cp.async.commit_group;" ::: "memory");
            av0 = *(const float4*)(A + (size_t)(row0 + aRow)      * K + k1 + aK4);
            av1 = *(const float4*)(A + (size_t)(row0 + aRow + 64) * K + k1 + aK4);
            asm volatile("cp.async.wait_group 1;" ::: "memory");
        } else {
            asm volatile("cp.async.wait_group 0;" ::: "memory");
        }
        __syncthreads();

#pragma unroll
        for (int kk = 0; kk < 16; kk++) {
            float4 a0 = *(const float4*)&As[cur][kk][ty * 8];
            float4 a1 = *(const float4*)&As[cur][kk][ty * 8 + 4];
            const ulonglong2* bp = (const ulonglong2*)&Bs[cur][kk][tx * 8];
            ulonglong2 b01 = bp[0];
            ulonglong2 b23 = bp[1];
            float av[8] = {a0.x, a0.y, a0.z, a0.w, a1.x, a1.y, a1.z, a1.w};
#pragma unroll
            for (int i = 0; i < 8; i++) {
                unsigned long long a2 = splat2(av[i]);
                acc[i][0] = ffma2(a2, b01.x, acc[i][0]);
                acc[i][1] = ffma2(a2, b01.y, acc[i][1]);
                acc[i][2] = ffma2(a2, b23.x, acc[i][2]);
                acc[i][3] = ffma2(a2, b23.y, acc[i][3]);
            }
        }

        if (it + 1 < nIter) {
            const int nb = cur ^ 1;
            As[nb][aK4 + 0][aRow] = av0.x;  As[nb][aK4 + 1][aRow] = av0.y;
            As[nb][aK4 + 2][aRow] = av0.z;  As[nb][aK4 + 3][aRow] = av0.w;
            As[nb][aK4 + 0][aRow + 64] = av1.x;  As[nb][aK4 + 1][aRow + 64] = av1.y;
            As[nb][aK4 + 2][aRow + 64] = av1.z;  As[nb][aK4 + 3][aRow + 64] = av1.w;
        }
        __syncthreads();
    }

    const int crow = row0 + ty * 8;
    const int ccol = col0 + tx * 8;
    float bsum[8];
#pragma unroll
    for (int j = 0; j < 8; j++) {
        float bv = b1p[ccol + j];
        if (b2p) bv += b2p[ccol + j];
        bsum[j] = bv;
    }
#pragma unroll
    for (int i = 0; i < 8; i++) {
        float o[8];
#pragma unroll
        for (int j4 = 0; j4 < 4; j4++) {
            float2 v = unpack2(acc[i][j4]);
            o[2 * j4]     = v.x + bsum[2 * j4];
            o[2 * j4 + 1] = v.y + bsum[2 * j4 + 1];
        }
        float4* cp = (float4*)(C + (size_t)(crow + i) * N + ccol);
        cp[0] = make_float4(o[0], o[1], o[2], o[3]);
        cp[1] = make_float4(o[4], o[5], o[6], o[7]);
    }
}

// ---------------------------------------------------------------------------
// h0 transpose: [B][H] -> g_hx[1] in [j][b] layout.  (scan step t=0 reads
// buffer (t+1)&1 = 1).  Also redundantly resets the barrier counter.
// ---------------------------------------------------------------------------
__global__ void h0_transpose_kernel(const float* __restrict__ h0)
{
    if (blockIdx.x == 0 && threadIdx.x == 0) g_bar = 0u;
    int idx = blockIdx.x * 256 + threadIdx.x;   // 32768 total
    int b = idx >> 10;
    int j = idx & 1023;
    g_hx[1][j * B_ + b] = h0[idx];
}

// ---------------------------------------------------------------------------
// Persistent RNN scan kernel: R11 exact (proven best, ~2.33ms) with two
// zero-risk micro-mods: __ldcg on h-exchange loads (L2-only: correct by
// construction for cross-SM data, frees L1) and no nanosleep in the poll.
//
// grid = 128 blocks (1 block/SM), block = 512 threads.
// Block owns j-columns [bx*8, bx*8+8); Wh slab (1024x8 = 32KB) dynamic smem.
// Thread map: warp = ks (16 k-splits of 64 k), lane = b (0..31).
// Barrier: fire-and-forget red.release arrival + ld.acquire poll; history
// stores sit between arrive and poll (off the inter-SM critical path).
// ---------------------------------------------------------------------------
__global__ __launch_bounds__(512, 1) void rnn_scan_kernel(
    const float* __restrict__ Wh,   // [H][H]
    float* __restrict__ next_h)     // [B][H]
{
    extern __shared__ __align__(16) float whs[];                  // 32KB [k][jl]
    __shared__ __align__(16) unsigned long long red[16][4][32];   // 16KB

    const int tid   = threadIdx.x;
    const int ks    = tid >> 5;       // 0..15  k-split (warp)
    const int b     = tid & 31;       // lane = batch row
    const int jbase = blockIdx.x * 8;
    const int k0    = ks * 64;

    // Load this block's Wh slab once (step-invariant).
    for (int idx = tid; idx < H_ * 8; idx += 512) {
        int k = idx >> 3, j = idx & 7;
        whs[idx] = Wh[(size_t)k * H_ + jbase + j];
    }
    __syncthreads();

    const float* wb = whs + (k0 << 3);    // warp-uniform weight base
    const int jp = tid >> 5;              // reduction role: j-pair (tid<128)
    const int rb = tid & 31;              //                 batch row
    const int j0 = jbase + 2 * jp;

    unsigned* bar_ptr = &g_bar;
    unsigned  target  = gridDim.x;

    for (int t = 0; t < T_; t++) {
        const float* hx = g_hx[(t + 1) & 1] + k0 * B_ + b;   // [k][b] slice
        float*       hw = g_hx[t & 1];

        // prefetch xp for this step (used by reduction threads later)
        unsigned long long xpv = 0ull;
        if (tid < 128)
            xpv = *(const unsigned long long*)
                  (g_xp + (size_t)rb * (T_ * H_) + t * H_ + j0);

        unsigned long long a0 = 0ull, a1 = 0ull, a2 = 0ull, a3 = 0ull;
#pragma unroll
        for (int c = 0; c < 4; c++) {
            float hv[16];
#pragma unroll
            for (int i = 0; i < 16; i++)
                hv[i] = __ldcg(hx + (c * 16 + i) * B_);     // L2-only
#pragma unroll
            for (int i = 0; i < 16; i++) {
                const int k = c * 16 + i;
                ulonglong2 w01 = *(const ulonglong2*)(wb + (k << 3));
                ulonglong2 w23 = *(const ulonglong2*)(wb + (k << 3) + 4);
                unsigned long long s_ = splat2(hv[i]);
                a0 = ffma2(s_, w01.x, a0);  a1 = ffma2(s_, w01.y, a1);
                a2 = ffma2(s_, w23.x, a2);  a3 = ffma2(s_, w23.y, a3);
            }
        }

        // partials -> smem   (layout [ks][jp][b]: conflict-free both ways)
        red[ks][0][b] = a0;  red[ks][1][b] = a1;
        red[ks][2][b] = a2;  red[ks][3][b] = a3;
        __syncthreads();

        float2 v = make_float2(0.f, 0.f);
        if (tid < 128) {
            unsigned long long s0 = add2(red[0][jp][rb],  red[1][jp][rb]);
            unsigned long long s1 = add2(red[2][jp][rb],  red[3][jp][rb]);
            unsigned long long s2 = add2(red[4][jp][rb],  red[5][jp][rb]);
            unsigned long long s3 = add2(red[6][jp][rb],  red[7][jp][rb]);
            unsigned long long s4 = add2(red[8][jp][rb],  red[9][jp][rb]);
            unsigned long long s5 = add2(red[10][jp][rb], red[11][jp][rb]);
            unsigned long long s6 = add2(red[12][jp][rb], red[13][jp][rb]);
            unsigned long long s7 = add2(red[14][jp][rb], red[15][jp][rb]);
            unsigned long long s  = add2(add2(add2(s0, s1), add2(s2, s3)),
                                         add2(add2(s4, s5), add2(s6, s7)));
            s = add2(s, xpv);

            v = unpack2(s);
            v.x = tanhf(v.x);
            v.y = tanhf(v.y);

            // coalesced exchange-buffer store (critical path)
            hw[j0 * B_ + rb]       = v.x;
            hw[(j0 + 1) * B_ + rb] = v.y;
        }

        // ---- grid barrier (release arrival, acquire poll) ----
        __syncthreads();
        if (tid == 0) {
            asm volatile("red.release.gpu.global.add.u32 [%0], %1;"
                         :: "l"(bar_ptr), "r"(1u) : "memory");
        }
        // history stores between arrive and poll: off the inter-SM path
        if (tid < 128) {
            *(float2*)(g_hs + (size_t)rb * (T_ * H_) + t * H_ + j0) = v;
            if (t == T_ - 1)
                *(float2*)(next_h + rb * H_ + j0) = v;
        }
        if (tid == 0) {
            unsigned e;
            do {
                asm volatile("ld.acquire.gpu.global.u32 %0, [%1];"
                             : "=r"(e) : "l"(bar_ptr) : "memory");
            } while (e < target);
        }
        __syncthreads();
        target += gridDim.x;
    }
}

// ---------------------------------------------------------------------------
// kernel_launch: 8 launches (3 no-op preludes for ncu alignment), all
// graph-capturable, default stream.
// Inputs: 0:x 1:h 2:Wx 3:bx 4:Wh 5:bh 6:W1 7:b1 8:W2 9:b2
// Output: [td0 (B*T*OUT) | td1 (B*T*OUT) | next_h (B*H)]
// ---------------------------------------------------------------------------
extern "C" void kernel_launch(void* const* d_in, const int* in_sizes, int n_in,
                              void* d_out, int out_size)
{
    (void)in_sizes; (void)n_in; (void)out_size;
    const float* x  = (const float*)d_in[0];
    const float* h  = (const float*)d_in[1];
    const float* Wx = (const float*)d_in[2];
    const float* bx = (const float*)d_in[3];
    const float* Wh = (const float*)d_in[4];
    const float* bh = (const float*)d_in[5];
    const float* W1 = (const float*)d_in[6];
    const float* b1 = (const float*)d_in[7];
    const float* W2 = (const float*)d_in[8];
    const float* b2 = (const float*)d_in[9];
    float* out = (float*)d_out;

    float* xp = nullptr;
    float* hs = nullptr;
    cudaGetSymbolAddress((void**)&xp, g_xp);
    cudaGetSymbolAddress((void**)&hs, g_hs);

    const int MT = B_ * T_;   // 16384

    // ncu capture alignment: launches 1-3 are no-ops so that the harness's
    // "-s 5 -c 1" profile lands on launch #6 == the scan kernel.
    noop_kernel<<<1, 32>>>();
    noop_kernel<<<1, 32>>>();
    noop_kernel<<<1, 32>>>();

    // Phase 0 (launch 4): Xp = x @ Wx + (bx + bh).   M=16384, N=1024, K=512
    {
        dim3 grid(H_ / 128, MT / 128);
        sgemm_bias_kernel<<<grid, 256>>>(x, Wx, bx, bh, xp, MT, H_, IN_);
    }

    // Phase 0b (launch 5): transpose h0 into [j][b] (+ barrier reset).
    h0_transpose_kernel<<<(B_ * H_) / 256, 256>>>(h);

    // Phase 1 (launch 6 == ncu target): sequential scan.
    {
        float* next_h = out + (size_t)2 * MT * OUT_;
        rnn_scan_kernel<<<128, 512, H_ * 8 * sizeof(float)>>>(Wh, next_h);
    }

    // Phase 2 (launches 7,8): td0/td1 GEMMs.  M=16384, N=512, K=1024
    {
        dim3 grid(OUT_ / 128, MT / 128);
        sgemm_bias_kernel<<<grid, 256>>>(hs, W1, b1, nullptr, out, MT, OUT_, H_);
        sgemm_bias_kernel<<<grid, 256>>>(hs, W2, b2, nullptr,
                                         out + (size_t)MT * OUT_, MT, OUT_, H_);
    }
}